// round 2
// baseline (speedup 1.0000x reference)
#include <cuda_runtime.h>
#include <cstdint>

// ForwardWarpStereo — B=8, C=3, H=720, W=1280, fp32.
// flow = (-disp, 0): y-flow is exactly 0 on an integer grid, so the bilinear
// 4-tap splat degenerates to a 2-tap 1-D splat within each row.
// Pass 1: global min(disp). Pass 2: one CTA per row, smem scatter-add of
// 5 channels {R*w, G*w, B*w, w, 1}, then finalize res = acc/max(mask,eps),
// occ = 1 - min(ones_acc, 1).

#define BATCH 8
#define HH    720
#define WW    1280
#define EPS_F 1e-6f
// log2(1.414)
#define L2WB  0.49978221f

__device__ unsigned int g_min_bits;

// Map float -> monotonically ordered uint (handles sign, though disp >= 0 here).
__device__ __forceinline__ unsigned int f2ord(float f) {
    unsigned int b = __float_as_uint(f);
    return (b & 0x80000000u) ? ~b : (b | 0x80000000u);
}
__device__ __forceinline__ float ord2f(unsigned int o) {
    unsigned int b = (o & 0x80000000u) ? (o & 0x7FFFFFFFu) : ~o;
    return __uint_as_float(b);
}

__global__ void reset_min_kernel() {
    g_min_bits = 0xFFFFFFFFu;
}

__global__ __launch_bounds__(256) void min_kernel(const float* __restrict__ disp, int n4) {
    // n4 = number of float4 elements
    const float4* __restrict__ d4 = reinterpret_cast<const float4*>(disp);
    unsigned int m = 0xFFFFFFFFu;
    for (int i = blockIdx.x * blockDim.x + threadIdx.x; i < n4; i += gridDim.x * blockDim.x) {
        float4 v = d4[i];
        m = min(m, f2ord(v.x));
        m = min(m, f2ord(v.y));
        m = min(m, f2ord(v.z));
        m = min(m, f2ord(v.w));
    }
    // warp reduce
    #pragma unroll
    for (int o = 16; o; o >>= 1)
        m = min(m, __shfl_xor_sync(0xFFFFFFFFu, m, o));
    __shared__ unsigned int sm[8];
    if ((threadIdx.x & 31) == 0) sm[threadIdx.x >> 5] = m;
    __syncthreads();
    if (threadIdx.x < 8) {
        unsigned int v = sm[threadIdx.x];
        #pragma unroll
        for (int o = 4; o; o >>= 1)
            v = min(v, __shfl_xor_sync(0x000000FFu, v, o));
        if (threadIdx.x == 0) atomicMin(&g_min_bits, v);
    }
}

__global__ __launch_bounds__(256) void warp_splat_kernel(
    const float* __restrict__ im,
    const float* __restrict__ disp,
    float* __restrict__ out)
{
    __shared__ float acc[5][WW];   // R, G, B, wmap(mask), ones(occ)

    const int row = blockIdx.x;        // 0 .. BATCH*HH-1
    const int b   = row / HH;
    const int y   = row - b * HH;
    const int tid = threadIdx.x;

    const float dmin = ord2f(g_min_bits);

    // zero accumulators
    float* accf = &acc[0][0];
    #pragma unroll
    for (int i = tid; i < 5 * WW; i += 256) accf[i] = 0.0f;
    __syncthreads();

    const size_t HWs = (size_t)HH * WW;
    const float* __restrict__ dRow = disp + ((size_t)b * HH + y) * WW;
    const float* __restrict__ rR   = im + (((size_t)b * 3 + 0) * HH + y) * WW;
    const float* __restrict__ rG   = rR + HWs;
    const float* __restrict__ rB   = rG + HWs;

    for (int x = tid; x < WW; x += 256) {
        float d  = dRow[x];
        float wm = exp2f((d - dmin) * L2WB);
        float xp = (float)x - d;
        float x0 = floorf(xp);
        int   i0 = (int)x0;
        float w1 = xp - x0;
        float w0 = 1.0f - w1;

        float vr = rR[x] * wm;
        float vg = rG[x] * wm;
        float vb = rB[x] * wm;

        if ((unsigned)i0 < (unsigned)WW) {
            atomicAdd(&acc[0][i0], vr * w0);
            atomicAdd(&acc[1][i0], vg * w0);
            atomicAdd(&acc[2][i0], vb * w0);
            atomicAdd(&acc[3][i0], wm * w0);
            atomicAdd(&acc[4][i0], w0);
        }
        int i1 = i0 + 1;
        if ((unsigned)i1 < (unsigned)WW) {
            atomicAdd(&acc[0][i1], vr * w1);
            atomicAdd(&acc[1][i1], vg * w1);
            atomicAdd(&acc[2][i1], vb * w1);
            atomicAdd(&acc[3][i1], wm * w1);
            atomicAdd(&acc[4][i1], w1);
        }
    }
    __syncthreads();

    float* __restrict__ oR = out + (((size_t)b * 3 + 0) * HH + y) * WW;
    float* __restrict__ oG = oR + HWs;
    float* __restrict__ oB = oG + HWs;
    float* __restrict__ oO = out + (size_t)BATCH * 3 * HWs + ((size_t)b * HH + y) * WW;

    for (int x = tid; x < WW; x += 256) {
        float m   = fmaxf(acc[3][x], EPS_F);
        float inv = 1.0f / m;
        oR[x] = acc[0][x] * inv;
        oG[x] = acc[1][x] * inv;
        oB[x] = acc[2][x] * inv;
        oO[x] = 1.0f - fminf(acc[4][x], 1.0f);
    }
}

extern "C" void kernel_launch(void* const* d_in, const int* in_sizes, int n_in,
                              void* d_out, int out_size)
{
    // Select inputs by size (im has 3x the elements of disp) — robust to
    // metadata ordering. im: B*3*H*W = 22,118,400; disp: B*1*H*W = 7,372,800.
    const float* im;
    const float* disp;
    int n_disp;
    if (in_sizes[0] >= in_sizes[1]) {
        im = (const float*)d_in[0];
        disp = (const float*)d_in[1];
        n_disp = in_sizes[1];
    } else {
        im = (const float*)d_in[1];
        disp = (const float*)d_in[0];
        n_disp = in_sizes[0];
    }
    float* out = (float*)d_out;

    reset_min_kernel<<<1, 1>>>();
    min_kernel<<<1440, 256>>>(disp, n_disp / 4);
    warp_splat_kernel<<<BATCH * HH, 256>>>(im, disp, out);
}